// round 2
// baseline (speedup 1.0000x reference)
#include <cuda_runtime.h>
#include <cuda_bf16.h>

// Problem constants (fixed by the dataset generator)
#define NXc 65
#define NYc 87
#define Vc  5655            // NXc*NYc
#define Bc  8
#define Sc  45240           // Bc*Vc
#define NMAX 1000000
#define EMAX 8000000

// ---------- device scratch (static; no runtime allocation allowed) ----------
__device__ int      g_cluster[NMAX];       // 4 MB  cluster id per node
__device__ int      g_node_cnt[Sc];
__device__ int      g_node_off[Sc + 1];
__device__ int      g_node_cur[Sc];
__device__ int      g_node_sorted[NMAX];   // 4 MB  node ids grouped by cluster
__device__ int      g_edge_cnt[Sc];
__device__ int      g_edge_off[Sc + 1];
__device__ int      g_edge_cur[Sc];
__device__ unsigned g_edge_c[EMAX];        // 32 MB  dst-cluster per edge, grouped by src-cluster

// ---------------------------------------------------------------------------
__global__ void k_zero()
{
    int i = blockIdx.x * blockDim.x + threadIdx.x;
    if (i < Sc) {
        g_node_cnt[i] = 0;
        g_edge_cnt[i] = 0;
    }
}

// cluster id per node + node histogram
__global__ void k_cluster(const float* __restrict__ pos,
                          const int* __restrict__ batch, int N)
{
    int i = blockIdx.x * blockDim.x + threadIdx.x;
    if (i >= N) return;
    float px = pos[(size_t)i * 3 + 0];
    float py = pos[(size_t)i * 3 + 1];
    int c0 = min(max((int)floorf(px * 0.25f), 0), NXc - 1);
    int c1 = min(max((int)floorf(py * 0.25f), 0), NYc - 1);
    int c  = batch[i] * Vc + c0 * NYc + c1;
    g_cluster[i] = c;
    atomicAdd(&g_node_cnt[c], 1);
}

// edge histogram over src cluster r
__global__ void k_edge_hist(const int* __restrict__ ei, int E)
{
    int e = blockIdx.x * blockDim.x + threadIdx.x;
    if (e >= E) return;
    int r = g_cluster[ei[e]];
    atomicAdd(&g_edge_cnt[r], 1);
}

// exclusive scan of the two Sc-sized histograms (block 0: nodes, block 1: edges)
__global__ void k_scan()
{
    __shared__ int wsum[32];
    int tid = threadIdx.x, lane = tid & 31, wid = tid >> 5;
    const int* cnt; int* off; int* cur;
    if (blockIdx.x == 0) { cnt = g_node_cnt; off = g_node_off; cur = g_node_cur; }
    else                 { cnt = g_edge_cnt; off = g_edge_off; cur = g_edge_cur; }

    int carry = 0;
    for (int base = 0; base < Sc; base += 1024) {
        int idx = base + tid;
        int v = (idx < Sc) ? cnt[idx] : 0;
        int s = v;
        #pragma unroll
        for (int d = 1; d < 32; d <<= 1) {
            int t = __shfl_up_sync(0xffffffffu, s, d);
            if (lane >= d) s += t;
        }
        if (lane == 31) wsum[wid] = s;
        __syncthreads();
        if (wid == 0) {
            int w = wsum[lane];
            #pragma unroll
            for (int d = 1; d < 32; d <<= 1) {
                int t = __shfl_up_sync(0xffffffffu, w, d);
                if (lane >= d) w += t;
            }
            wsum[lane] = w;
        }
        __syncthreads();
        int pre  = (wid > 0 ? wsum[wid - 1] : 0) + carry;
        int excl = pre + s - v;
        if (idx < Sc) { off[idx] = excl; cur[idx] = excl; }
        int total = wsum[31];
        __syncthreads();          // wsum reused next iteration
        carry += total;
    }
    if (tid == 0) off[Sc] = carry;
}

// scatter node indices grouped by cluster
__global__ void k_node_scatter(int N)
{
    int i = blockIdx.x * blockDim.x + threadIdx.x;
    if (i >= N) return;
    int c = g_cluster[i];
    int p = atomicAdd(&g_node_cur[c], 1);
    g_node_sorted[p] = i;
}

// scatter edge dst-clusters grouped by src-cluster
__global__ void k_edge_scatter(const int* __restrict__ ei, int E)
{
    int e = blockIdx.x * blockDim.x + threadIdx.x;
    if (e >= E) return;
    int r = g_cluster[ei[e]];
    unsigned c = (unsigned)g_cluster[ei[e + E]];
    int p = atomicAdd(&g_edge_cur[r], 1);
    g_edge_c[p] = c;
}

// per-bucket sort of dst clusters + emit edge_out rows (dedup + self-loop drop)
__global__ void k_edge_sort(float* __restrict__ out_e0,
                            float* __restrict__ out_e1)
{
    __shared__ unsigned sh[4096];
    int r     = blockIdx.x;
    int start = g_edge_off[r];
    int cnt   = g_edge_off[r + 1] - start;
    if (cnt <= 0) return;

    if (cnt <= 4096) {
        int M = 1;
        while (M < cnt) M <<= 1;
        for (int j = threadIdx.x; j < M; j += blockDim.x)
            sh[j] = (j < cnt) ? g_edge_c[start + j] : 0xFFFFFFFFu;
        __syncthreads();
        for (int k = 2; k <= M; k <<= 1) {
            for (int j = k >> 1; j > 0; j >>= 1) {
                for (int i = threadIdx.x; i < M; i += blockDim.x) {
                    int l = i ^ j;
                    if (l > i) {
                        unsigned a = sh[i], b = sh[l];
                        bool swap = ((i & k) == 0) ? (a > b) : (a < b);
                        if (swap) { sh[i] = b; sh[l] = a; }
                    }
                }
                __syncthreads();
            }
        }
        float fr = (float)r;
        for (int j = threadIdx.x; j < cnt; j += blockDim.x) {
            unsigned c = sh[j];
            bool valid = (j == 0 || sh[j - 1] != c) && (c != (unsigned)r);
            out_e0[start + j] = valid ? fr : -1.0f;
            out_e1[start + j] = valid ? (float)c : -1.0f;
        }
    } else {
        // statistically unreachable fallback: odd-even transposition in gmem
        for (int pass = 0; pass < cnt; pass++) {
            int par = pass & 1;
            for (int i = threadIdx.x * 2 + par; i + 1 < cnt; i += blockDim.x * 2) {
                unsigned a = g_edge_c[start + i], b = g_edge_c[start + i + 1];
                if (a > b) { g_edge_c[start + i] = b; g_edge_c[start + i + 1] = a; }
            }
            __syncthreads();
        }
        float fr = (float)r;
        for (int j = threadIdx.x; j < cnt; j += blockDim.x) {
            unsigned c = g_edge_c[start + j];
            bool valid = (j == 0 || g_edge_c[start + j - 1] != c) && (c != (unsigned)r);
            out_e0[start + j] = valid ? fr : -1.0f;
            out_e1[start + j] = valid ? (float)c : -1.0f;
        }
    }
}

// one warp per cluster: 64-feature max, pos mean, batch id, mask
__global__ void k_reduce(const float* __restrict__ x,
                         const float* __restrict__ pos,
                         float* __restrict__ out_x,
                         float* __restrict__ out_pos,
                         float* __restrict__ out_batch,
                         float* __restrict__ out_mask)
{
    int gwarp = (blockIdx.x * blockDim.x + threadIdx.x) >> 5;
    int lane  = threadIdx.x & 31;
    if (gwarp >= Sc) return;
    int c     = gwarp;
    int start = g_node_off[c];
    int cnt   = g_node_off[c + 1] - start;

    float m0 = -3.402823466e38f, m1 = -3.402823466e38f;
    for (int k = 0; k < cnt; k++) {
        int n = g_node_sorted[start + k];
        const float* row = x + (size_t)n * 64;
        m0 = fmaxf(m0, row[lane]);
        m1 = fmaxf(m1, row[lane + 32]);
    }
    float p0 = 0.f, p1 = 0.f, p2 = 0.f;
    for (int k = lane; k < cnt; k += 32) {
        int n = g_node_sorted[start + k];
        const float* pr = pos + (size_t)n * 3;
        p0 += pr[0]; p1 += pr[1]; p2 += pr[2];
    }
    #pragma unroll
    for (int d = 16; d > 0; d >>= 1) {
        p0 += __shfl_down_sync(0xffffffffu, p0, d);
        p1 += __shfl_down_sync(0xffffffffu, p1, d);
        p2 += __shfl_down_sync(0xffffffffu, p2, d);
    }
    bool occ = cnt > 0;
    out_x[(size_t)c * 64 + lane]      = occ ? m0 : 0.0f;
    out_x[(size_t)c * 64 + lane + 32] = occ ? m1 : 0.0f;
    if (lane == 0) {
        float den = fmaxf((float)cnt, 1.0f);
        out_pos[(size_t)c * 3 + 0] = p0 / den;
        out_pos[(size_t)c * 3 + 1] = p1 / den;
        out_pos[(size_t)c * 3 + 2] = p2 / den;
        out_batch[c] = (float)(c / Vc);
        out_mask[c]  = occ ? 1.0f : 0.0f;
    }
}

// ---------------------------------------------------------------------------
extern "C" void kernel_launch(void* const* d_in, const int* in_sizes, int n_in,
                              void* d_out, int out_size)
{
    const float* x     = (const float*)d_in[0];
    const float* pos   = (const float*)d_in[1];
    const int*   batch = (const int*)d_in[2];
    const int*   ei    = (const int*)d_in[3];
    float*       out   = (float*)d_out;

    int N = in_sizes[0] / 64;
    int E = in_sizes[3] / 2;

    // output layout: x_pool[S,64] | pos_pool[S,3] | batch_out[S] | edge_out[2,E] | mask[S]
    size_t OFF_POS   = (size_t)Sc * 64;
    size_t OFF_BATCH = OFF_POS + (size_t)Sc * 3;
    size_t OFF_EDGE  = OFF_BATCH + Sc;
    size_t OFF_MASK  = OFF_EDGE + (size_t)2 * E;

    k_zero<<<(Sc + 255) / 256, 256>>>();
    k_cluster<<<(N + 255) / 256, 256>>>(pos, batch, N);
    k_edge_hist<<<(E + 511) / 512, 512>>>(ei, E);
    k_scan<<<2, 1024>>>();
    k_node_scatter<<<(N + 255) / 256, 256>>>(N);
    k_edge_scatter<<<(E + 511) / 512, 512>>>(ei, E);
    k_edge_sort<<<Sc, 256>>>(out + OFF_EDGE, out + OFF_EDGE + E);
    k_reduce<<<(Sc * 32 + 127) / 128, 128>>>(x, pos,
                                             out, out + OFF_POS,
                                             out + OFF_BATCH, out + OFF_MASK);
    (void)n_in; (void)out_size;
}